// round 16
// baseline (speedup 1.0000x reference)
#include <cuda_runtime.h>
#include <cuda_fp16.h>
#include <math.h>
#include <cstdint>

#define Bb 64
#define Ll 12
#define Nn 4096
#define Cc 3
#define FDm 32
#define HDm 64
#define OUTD 12
#define TIDn 288
#define DIWn 7
#define TDm 16
#define NSTEPS 4
#define EMBm 10
#define BF (Bb*FDm)   // 2048

// Scratch (device globals)
__device__ float g_field[(size_t)Nn*BF];                    // field[m][j], j=b*32+f
__device__ float g_state[(size_t)Nn*BF];
__device__ __align__(16) __half g_Ah[(size_t)Nn*Nn];        // A fp16 [n][m]
__device__ __align__(16) __half g_Fh[2][(size_t)Nn*BF];     // field fp16 [m][j], dbl-buf

// ------------------------------ PTX helpers -------------------------------
__device__ __forceinline__ uint32_t smem_to_u32(const void* p) {
    uint32_t a;
    asm("{ .reg .u64 t; cvta.to.shared.u64 t, %1; cvt.u32.u64 %0, t; }"
        : "=r"(a) : "l"(p));
    return a;
}
__device__ __forceinline__ void cp16(uint32_t dst, const void* src) {
    asm volatile("cp.async.cg.shared.global [%0], [%1], 16;" :: "r"(dst), "l"(src));
}
#define CP_COMMIT() asm volatile("cp.async.commit_group;" ::: "memory")
#define CP_WAIT(n)  asm volatile("cp.async.wait_group %0;" :: "n"(n) : "memory")

__device__ __forceinline__ void ldsm4(uint32_t* r, uint32_t addr) {
    asm volatile("ldmatrix.sync.aligned.m8n8.x4.shared.b16 {%0,%1,%2,%3}, [%4];"
                 : "=r"(r[0]), "=r"(r[1]), "=r"(r[2]), "=r"(r[3]) : "r"(addr));
}
__device__ __forceinline__ void ldsm4t(uint32_t* r, uint32_t addr) {
    asm volatile("ldmatrix.sync.aligned.m8n8.x4.trans.shared.b16 {%0,%1,%2,%3}, [%4];"
                 : "=r"(r[0]), "=r"(r[1]), "=r"(r[2]), "=r"(r[3]) : "r"(addr));
}
__device__ __forceinline__ void mma_f16(float* c, const uint32_t* a, const uint32_t* b) {
    asm volatile("mma.sync.aligned.m16n8k16.row.col.f32.f16.f16.f32 "
                 "{%0,%1,%2,%3}, {%4,%5,%6,%7}, {%8,%9}, {%0,%1,%2,%3};"
                 : "+f"(c[0]), "+f"(c[1]), "+f"(c[2]), "+f"(c[3])
                 : "r"(a[0]), "r"(a[1]), "r"(a[2]), "r"(a[3]), "r"(b[0]), "r"(b[1]));
}

// ---------------------------------------------------------------------------
// MERGED PROLOGUE: blocks [0, BA_BLOCKS) build A via flash-softmax (emb tiled
// through SMEM, 32 rows/block, 8 lanes/row); blocks [BA_BLOCKS, +ENC_BLOCKS)
// run the encoder (grid-stride warp-per-point).
// ---------------------------------------------------------------------------
#define BA_BLOCKS 128
#define BA_NPB 32
#define BA_CH 1024
#define ENC_BLOCKS 512

__global__ void __launch_bounds__(256) prologue_kernel(
    const float* __restrict__ emb,
    const float* __restrict__ hist,
    const float* __restrict__ tid_emb, const float* __restrict__ diw_emb,
    const float* __restrict__ t2f_w,   const float* __restrict__ t2f_b,
    const float* __restrict__ w1, const float* __restrict__ b1,
    const float* __restrict__ w2, const float* __restrict__ b2)
{
    __shared__ __align__(16) char sbuf[BA_CH * EMBm * 4];   // 40960 B
    int tid = threadIdx.x;

    if (blockIdx.x < BA_BLOCKS) {
        float* semb = (float*)sbuf;
        int nl = tid >> 3;
        int ml = tid & 7;
        int n = blockIdx.x * BA_NPB + nl;

        float en[EMBm];
        {
            const float2* ep = (const float2*)(emb + (size_t)n * EMBm);
            #pragma unroll
            for (int k = 0; k < 5; k++) {
                float2 v = ep[k];
                en[2*k] = v.x; en[2*k+1] = v.y;
            }
        }

        float mx = 0.f, sum = 0.f;                  // relu >= 0
        for (int c = 0; c < Nn / BA_CH; c++) {
            const float4* src = (const float4*)(emb + (size_t)c * BA_CH * EMBm);
            float4* dst = (float4*)semb;
            #pragma unroll
            for (int k = 0; k < (BA_CH*EMBm/4)/256; k++)
                dst[tid + k*256] = src[tid + k*256];
            __syncthreads();
            #pragma unroll 4
            for (int i = 0; i < BA_CH/8; i++) {
                int m = i*8 + ml;
                const float2* sp = (const float2*)(semb + m * EMBm);
                float2 p0 = sp[0], p1 = sp[1], p2 = sp[2], p3 = sp[3], p4 = sp[4];
                float d = en[0]*p0.x + en[1]*p0.y + en[2]*p1.x + en[3]*p1.y
                        + en[4]*p2.x + en[5]*p2.y + en[6]*p3.x + en[7]*p3.y
                        + en[8]*p4.x + en[9]*p4.y;
                d = fmaxf(d, 0.f);
                if (d > mx) { sum *= expf(mx - d); mx = d; }
                sum += expf(d - mx);
            }
            __syncthreads();
        }
        #pragma unroll
        for (int o = 1; o < 8; o <<= 1) {
            float m2 = __shfl_xor_sync(0xffffffffu, mx, o);
            float s2 = __shfl_xor_sync(0xffffffffu, sum, o);
            float M = fmaxf(mx, m2);
            sum = sum * expf(mx - M) + s2 * expf(m2 - M);
            mx = M;
        }
        float inv = 1.f / sum;

        for (int c = 0; c < Nn / BA_CH; c++) {
            const float4* src = (const float4*)(emb + (size_t)c * BA_CH * EMBm);
            float4* dst = (float4*)semb;
            #pragma unroll
            for (int k = 0; k < (BA_CH*EMBm/4)/256; k++)
                dst[tid + k*256] = src[tid + k*256];
            __syncthreads();
            #pragma unroll 4
            for (int i = 0; i < BA_CH/8; i++) {
                int m = i*8 + ml;
                const float2* sp = (const float2*)(semb + m * EMBm);
                float2 p0 = sp[0], p1 = sp[1], p2 = sp[2], p3 = sp[3], p4 = sp[4];
                float d = en[0]*p0.x + en[1]*p0.y + en[2]*p1.x + en[3]*p1.y
                        + en[4]*p2.x + en[5]*p2.y + en[6]*p3.x + en[7]*p3.y
                        + en[8]*p4.x + en[9]*p4.y;
                d = fmaxf(d, 0.f);
                g_Ah[(size_t)n*Nn + c*BA_CH + m] = __float2half_rn(expf(d - mx) * inv);
            }
            __syncthreads();
        }
        return;
    }

    // ----------------- encoder -----------------
    float* s_w1  = (float*)sbuf;
    float* s_w2  = s_w1 + Ll*Cc*HDm;
    float* s_t2f = s_w2 + HDm*FDm;
    float* s_b1  = s_t2f + 2*TDm*FDm;
    float* s_b2  = s_b1 + HDm;
    float* s_t2fb= s_b2 + FDm;

    for (int i = tid; i < Ll*Cc*HDm; i += 256) s_w1[i] = w1[i];
    for (int i = tid; i < HDm*FDm;   i += 256) s_w2[i] = w2[i];
    for (int i = tid; i < 2*TDm*FDm; i += 256) s_t2f[i] = t2f_w[i];
    if (tid < HDm) s_b1[tid] = b1[tid];
    if (tid < FDm) { s_b2[tid] = b2[tid]; s_t2fb[tid] = t2f_b[tid]; }
    __syncthreads();

    int lane = tid & 31;
    int gw = ((blockIdx.x - BA_BLOCKS) * 256 + tid) >> 5;

    for (int it = 0; it < (Bb*Nn)/(ENC_BLOCKS*8); it++) {
        int P = it * (ENC_BLOCKS*8) + gw;
        int n = P & (Nn - 1);
        int b = P >> 12;

        const float* hb = hist + ((size_t)b * Ll * Nn + n) * Cc;
        float x[Ll*Cc];
        #pragma unroll
        for (int l = 0; l < Ll; l++)
            #pragma unroll
            for (int c = 0; c < Cc; c++)
                x[l*Cc + c] = hb[(size_t)l * Nn * Cc + c];

        float h0 = s_b1[lane], h1 = s_b1[32 + lane];
        #pragma unroll
        for (int k = 0; k < Ll*Cc; k++) {
            h0 = fmaf(x[k], s_w1[k*HDm + lane],      h0);
            h1 = fmaf(x[k], s_w1[k*HDm + 32 + lane], h1);
        }
        h0 = fmaxf(h0, 0.f); h1 = fmaxf(h1, 0.f);

        float acc = s_b2[lane];
        #pragma unroll
        for (int hh = 0; hh < HDm; hh++) {
            float v = __shfl_sync(0xffffffffu, (hh < 32) ? h0 : h1, hh & 31);
            acc = fmaf(v, s_w2[hh*FDm + lane], acc);
        }

        float v1 = hb[(size_t)(Ll-1)*Nn*Cc + 1];
        float v2 = hb[(size_t)(Ll-1)*Nn*Cc + 2];
        int ti = (int)(v1 * (float)TIDn); ti = min(max(ti, 0), TIDn-1);
        int di = (int)(v2 * (float)DIWn); di = min(max(di, 0), DIWn-1);
        #pragma unroll
        for (int k = 0; k < TDm; k++)
            acc = fmaf(tid_emb[ti*TDm + k], s_t2f[k*FDm + lane], acc);
        #pragma unroll
        for (int k = 0; k < TDm; k++)
            acc = fmaf(diw_emb[di*TDm + k], s_t2f[(TDm + k)*FDm + lane], acc);
        acc += s_t2fb[lane];

        size_t off = (size_t)n * BF + b*FDm + lane;
        g_field[off] = acc;
        g_Fh[0][off] = __float2half_rn(acc);
    }
}

// ---------------------------------------------------------------------------
// FUSED: fp16 GEMM (AF = A @ field) + step-MLP epilogue (+decoder on last).
// CTA 128x128, BK=32, 5-stage cp.async pipeline (distance-4), 2 CTAs/SM.
// Interleaved per-kk fragment loads (proven-best inner loop).
// ---------------------------------------------------------------------------
#define BKg 32
#define LDAe 40
#define TA_BYTES (128*LDAe*2)          // 10240
#define LDBB 136
#define TB_BYTES (BKg*LDBB*2)          // 8704
#define STG_BYTES (TA_BYTES + TB_BYTES)  // 18944
#define NST 5
#define CSM_PITCH 132
#define CSM_BYTES (128*CSM_PITCH*4)    // 67584
#define WGT_FLOATS (2048+2048+3*1024+160+2048+64+768+12)   // 10220
#define GSMEM (CSM_BYTES + WGT_FLOATS*4)                   // 108464 (>= 5*18944)

__global__ void __launch_bounds__(256, 2) gemm_fused(
    const float* __restrict__ pw1, const float* __restrict__ pb1,
    const float* __restrict__ pw2, const float* __restrict__ pb2,
    const float* __restrict__ win, const float* __restrict__ wst,
    const float* __restrict__ sb,  const float* __restrict__ wout,
    const float* __restrict__ bout, const float* __restrict__ pde_mix,
    const float* __restrict__ dw1, const float* __restrict__ db1,
    const float* __restrict__ dw2, const float* __restrict__ db2,
    float* __restrict__ out,
    int first, int last, int rbuf)
{
    extern __shared__ char smem[];
    uint32_t sbase = smem_to_u32(smem);
    int tid = threadIdx.x;
    int lane = tid & 31;
    int wid = tid >> 5;
    int bcol = blockIdx.x;    // 0..15
    int brow = blockIdx.y;    // 0..31

    const __half* Ah = g_Ah + (size_t)brow * 128 * Nn;
    const __half* Bg = g_Fh[rbuf] + (size_t)bcol * 128;

    int alr = tid >> 1;
    int alc = (tid & 1) * 16;
    size_t gA = (size_t)alr * Nn + alc;
    uint32_t sA = sbase + alr * (LDAe*2) + alc * 2;
    int blr = tid >> 3;
    int blc = (tid & 7) * 16;
    uint32_t sB = sbase + TA_BYTES + blr * (LDBB*2) + blc * 2;

    int warp_m = wid & 1;
    int warp_n = wid >> 1;
    int m_base = warp_m * 64;
    int n_base = warp_n * 32;

    float acc[4][4][4];
    #pragma unroll
    for (int i = 0; i < 4; i++)
        #pragma unroll
        for (int j = 0; j < 4; j++)
            #pragma unroll
            for (int q = 0; q < 4; q++) acc[i][j][q] = 0.f;

    uint32_t a_off[4];
    #pragma unroll
    for (int i = 0; i < 4; i++)
        a_off[i] = (m_base + i*16 + (lane & 15)) * (LDAe*2) + ((lane >> 4) * 8) * 2;
    uint32_t b_off[2];
    {
        int i = lane >> 3;
        #pragma unroll
        for (int nj = 0; nj < 2; nj++)
            b_off[nj] = ((i & 1) * 8 + (lane & 7)) * (LDBB*2)
                      + (n_base + nj*16 + (i >> 1) * 8) * 2;
    }

    const int NIT = Nn / BKg;   // 128

    // prefetch stages 0..3 (distance-4 pipeline)
    #pragma unroll
    for (int p = 0; p < 4; p++) {
        uint32_t d = p * STG_BYTES;
        size_t kg = (size_t)p * BKg;
        cp16(sA + d,              Ah + gA + kg); cp16(sA + d + 16,              Ah + gA + kg + 8);
        const __half* bs = Bg + (kg + blr) * BF + blc;
        cp16(sB + d,              bs);           cp16(sB + d + 16,              bs + 8);
        CP_COMMIT();
    }

    int scur = 0, spre = 4;
    for (int it = 0; it < NIT; it++) {
        CP_WAIT(3);
        __syncthreads();

        if (it + 4 < NIT) {
            uint32_t d = spre * STG_BYTES;
            size_t kg = (size_t)(it + 4) * BKg;
            cp16(sA + d,              Ah + gA + kg); cp16(sA + d + 16,              Ah + gA + kg + 8);
            const __half* bs = Bg + (kg + blr) * BF + blc;
            cp16(sB + d,              bs);           cp16(sB + d + 16,              bs + 8);
        }
        CP_COMMIT();

        uint32_t st = sbase + scur * STG_BYTES;
        #pragma unroll
        for (int kk = 0; kk < 2; kk++) {
            uint32_t koff = kk * 32;
            uint32_t af[4][4];
            #pragma unroll
            for (int i = 0; i < 4; i++)
                ldsm4(af[i], st + a_off[i] + koff);
            uint32_t bf[2][4];
            #pragma unroll
            for (int j = 0; j < 2; j++)
                ldsm4t(bf[j], st + TA_BYTES + b_off[j] + kk * 16 * (LDBB*2));
            #pragma unroll
            for (int i = 0; i < 4; i++)
                #pragma unroll
                for (int na = 0; na < 4; na++)
                    mma_f16(acc[i][na], af[i], &bf[na >> 1][(na & 1) * 2]);
        }
        scur = (scur + 1 < NST) ? scur + 1 : 0;
        spre = (spre + 1 < NST) ? spre + 1 : 0;
    }
    CP_WAIT(0);
    __syncthreads();

    // ---------------- epilogue ----------------
    float* Csm  = (float*)smem;                 // [128][132]
    float* sw1  = (float*)(smem + CSM_BYTES);
    float* sw2  = sw1 + 2048;
    float* swin = sw2 + 2048;
    float* swst = swin + 1024;
    float* swou = swst + 1024;
    float* sbia = swou + 1024;                  // b1[64] b2[32] sb[32] bout[32]
    float* sdw1 = sbia + 160;
    float* sdb1 = sdw1 + 2048;
    float* sdw2 = sdb1 + 64;
    float* sdb2 = sdw2 + 768;

    for (int i = tid; i < 2048; i += 256) { sw1[i] = pw1[i]; sw2[i] = pw2[i]; }
    for (int i = tid; i < 1024; i += 256) { swin[i] = win[i]; swst[i] = wst[i]; swou[i] = wout[i]; }
    if (tid < 64) sbia[tid] = pb1[tid];
    if (tid < 32) { sbia[64+tid] = pb2[tid]; sbia[96+tid] = sb[tid]; sbia[128+tid] = bout[tid]; }
    if (last) {
        for (int i = tid; i < 2048; i += 256) sdw1[i] = dw1[i];
        for (int i = tid; i < 768;  i += 256) sdw2[i] = dw2[i];
        if (tid < 64) sdb1[tid] = db1[tid];
        if (tid < OUTD) sdb2[tid] = db2[tid];
    }

    #pragma unroll
    for (int i = 0; i < 4; i++) {
        int r = m_base + i*16 + (lane >> 2);
        #pragma unroll
        for (int na = 0; na < 4; na++) {
            int c = n_base + na*8 + 2*(lane & 3);
            Csm[r*CSM_PITCH + c]       = acc[i][na][0];
            Csm[r*CSM_PITCH + c + 1]   = acc[i][na][1];
            Csm[(r+8)*CSM_PITCH + c]   = acc[i][na][2];
            Csm[(r+8)*CSM_PITCH + c+1] = acc[i][na][3];
        }
    }
    __syncthreads();

    float alpha = 1.f / (1.f + expf(-pde_mix[0]));
    const float dtc = 1.f / NSTEPS;
    int wbuf = rbuf ^ 1;

    #pragma unroll
    for (int q = 0; q < 2; q++) {
        int P = q * 256 + tid;
        int m_loc = P >> 2;
        int bg = P & 3;
        int n_glob = brow*128 + m_loc;
        int b_glob = bcol*4 + bg;
        size_t pidx = (size_t)n_glob * Bb + b_glob;
        float* fb = g_field + pidx * FDm;
        float* sg = g_state + pidx * FDm;
        __half* fh = g_Fh[wbuf] + pidx * FDm;
        const float* crow = Csm + m_loc * CSM_PITCH + bg * 32;

        float x[FDm];
        #pragma unroll
        for (int i = 0; i < 8; i++) *(float4*)&x[i*4] = *(const float4*)(fb + i*4);

        float nf[FDm];
        #pragma unroll
        for (int f = 0; f < FDm; f++) nf[f] = sbia[64 + f];
        #pragma unroll
        for (int half = 0; half < 2; half++) {
            float h[32];
            #pragma unroll
            for (int hh = 0; hh < 32; hh++) h[hh] = sbia[half*32 + hh];
            #pragma unroll
            for (int k = 0; k < FDm; k++) {
                float xk = x[k];
                #pragma unroll
                for (int hh = 0; hh < 32; hh++)
                    h[hh] = fmaf(xk, sw1[k*HDm + half*32 + hh], h[hh]);
            }
            #pragma unroll
            for (int hh = 0; hh < 32; hh++) {
                float hv = fmaxf(h[hh], 0.f);
                #pragma unroll
                for (int f = 0; f < FDm; f++)
                    nf[f] = fmaf(hv, sw2[(half*32 + hh)*FDm + f], nf[f]);
            }
        }

        #pragma unroll
        for (int f = 0; f < FDm; f++) {
            float af2 = crow[f];
            x[f] = x[f] + (alpha*(af2 - x[f]) + (1.f - alpha)*nf[f]) * dtc;
        }

        float stv[FDm];
        if (first) {
            #pragma unroll
            for (int f = 0; f < FDm; f++) stv[f] = 0.f;
        } else {
            #pragma unroll
            for (int i = 0; i < 8; i++) *(float4*)&stv[i*4] = *(const float4*)(sg + i*4);
        }

        float sa[FDm];
        #pragma unroll
        for (int f = 0; f < FDm; f++) sa[f] = sbia[96 + f];
        #pragma unroll
        for (int k = 0; k < FDm; k++) {
            float fk = x[k], sk = stv[k];
            #pragma unroll
            for (int f = 0; f < FDm; f++) {
                sa[f] = fmaf(fk, swin[k*FDm + f], sa[f]);
                sa[f] = fmaf(sk, swst[k*FDm + f], sa[f]);
            }
        }
        #pragma unroll
        for (int f = 0; f < FDm; f++) sa[f] = tanhf(sa[f]);

        float fo[FDm];
        #pragma unroll
        for (int f = 0; f < FDm; f++) fo[f] = x[f] + sbia[128 + f];
        #pragma unroll
        for (int k = 0; k < FDm; k++) {
            float sk = sa[k];
            #pragma unroll
            for (int f = 0; f < FDm; f++)
                fo[f] = fmaf(sk, swou[k*FDm + f], fo[f]);
        }

        if (!last) {
            #pragma unroll
            for (int i = 0; i < 8; i++) *(float4*)(sg + i*4) = *(float4*)&sa[i*4];
            #pragma unroll
            for (int i = 0; i < 8; i++) *(float4*)(fb + i*4) = *(float4*)&fo[i*4];
            #pragma unroll
            for (int f = 0; f < FDm; f += 2)
                *(__half2*)(fh + f) = __floats2half2_rn(fo[f], fo[f+1]);
        } else {
            float pred[OUTD];
            #pragma unroll
            for (int o = 0; o < OUTD; o++) pred[o] = sdb2[o];
            #pragma unroll
            for (int half = 0; half < 2; half++) {
                float hd[32];
                #pragma unroll
                for (int hh = 0; hh < 32; hh++) hd[hh] = sdb1[half*32 + hh];
                #pragma unroll
                for (int k = 0; k < FDm; k++) {
                    float fk = fo[k];
                    #pragma unroll
                    for (int hh = 0; hh < 32; hh++)
                        hd[hh] = fmaf(fk, sdw1[k*HDm + half*32 + hh], hd[hh]);
                }
                #pragma unroll
                for (int hh = 0; hh < 32; hh++) {
                    float hv = fmaxf(hd[hh], 0.f);
                    #pragma unroll
                    for (int o = 0; o < OUTD; o++)
                        pred[o] = fmaf(hv, sdw2[(half*32 + hh)*OUTD + o], pred[o]);
                }
            }
            #pragma unroll
            for (int o = 0; o < OUTD; o++)
                out[((size_t)b_glob*OUTD + o)*Nn + n_glob] = pred[o];
        }
    }
}

// ---------------------------------------------------------------------------
extern "C" void kernel_launch(void* const* d_in, const int* in_sizes, int n_in,
                              void* d_out, int out_size)
{
    const float* hist     = (const float*)d_in[0];
    const float* tid_emb  = (const float*)d_in[5];
    const float* diw_emb  = (const float*)d_in[6];
    const float* t2f_w    = (const float*)d_in[7];
    const float* t2f_b    = (const float*)d_in[8];
    const float* enc_w1   = (const float*)d_in[9];
    const float* enc_b1   = (const float*)d_in[10];
    const float* enc_w2   = (const float*)d_in[11];
    const float* enc_b2   = (const float*)d_in[12];
    const float* node_emb = (const float*)d_in[13];
    const float* pde_w1   = (const float*)d_in[14];
    const float* pde_b1   = (const float*)d_in[15];
    const float* pde_w2   = (const float*)d_in[16];
    const float* pde_b2   = (const float*)d_in[17];
    const float* ss_win   = (const float*)d_in[18];
    const float* ss_wst   = (const float*)d_in[19];
    const float* ss_b     = (const float*)d_in[20];
    const float* ss_wout  = (const float*)d_in[21];
    const float* ss_bout  = (const float*)d_in[22];
    const float* dec_w1   = (const float*)d_in[23];
    const float* dec_b1   = (const float*)d_in[24];
    const float* dec_w2   = (const float*)d_in[25];
    const float* dec_b2   = (const float*)d_in[26];
    const float* pde_mix  = (const float*)d_in[27];

    static int smem_set = 0;
    if (!smem_set) {
        cudaFuncSetAttribute(gemm_fused, cudaFuncAttributeMaxDynamicSharedMemorySize, GSMEM);
        smem_set = 1;
    }

    prologue_kernel<<<BA_BLOCKS + ENC_BLOCKS, 256>>>(
        node_emb, hist, tid_emb, diw_emb, t2f_w, t2f_b,
        enc_w1, enc_b1, enc_w2, enc_b2);

    for (int s = 0; s < NSTEPS; s++) {
        gemm_fused<<<dim3(BF/128, Nn/128), 256, GSMEM>>>(
            pde_w1, pde_b1, pde_w2, pde_b2,
            ss_win, ss_wst, ss_b, ss_wout, ss_bout, pde_mix,
            dec_w1, dec_b1, dec_w2, dec_b2, (float*)d_out,
            s == 0, s == NSTEPS-1, s & 1);
    }
}

// round 17
// speedup vs baseline: 1.0271x; 1.0271x over previous
#include <cuda_runtime.h>
#include <cuda_fp16.h>
#include <math.h>
#include <cstdint>

#define Bb 64
#define Ll 12
#define Nn 4096
#define Cc 3
#define FDm 32
#define HDm 64
#define OUTD 12
#define TIDn 288
#define DIWn 7
#define TDm 16
#define NSTEPS 4
#define EMBm 10
#define BF (Bb*FDm)   // 2048

// Scratch (device globals)
__device__ float g_state[(size_t)Nn*BF];
__device__ __align__(16) __half g_Ah[(size_t)Nn*Nn];        // A fp16 [n][m]
__device__ __align__(16) __half g_Fh[2][(size_t)Nn*BF];     // field fp16 [m][j], dbl-buf

// ------------------------------ PTX helpers -------------------------------
__device__ __forceinline__ uint32_t smem_to_u32(const void* p) {
    uint32_t a;
    asm("{ .reg .u64 t; cvta.to.shared.u64 t, %1; cvt.u32.u64 %0, t; }"
        : "=r"(a) : "l"(p));
    return a;
}
__device__ __forceinline__ void cp16(uint32_t dst, const void* src) {
    asm volatile("cp.async.cg.shared.global [%0], [%1], 16;" :: "r"(dst), "l"(src));
}
#define CP_COMMIT() asm volatile("cp.async.commit_group;" ::: "memory")
#define CP_WAIT(n)  asm volatile("cp.async.wait_group %0;" :: "n"(n) : "memory")

__device__ __forceinline__ void ldsm4(uint32_t* r, uint32_t addr) {
    asm volatile("ldmatrix.sync.aligned.m8n8.x4.shared.b16 {%0,%1,%2,%3}, [%4];"
                 : "=r"(r[0]), "=r"(r[1]), "=r"(r[2]), "=r"(r[3]) : "r"(addr));
}
__device__ __forceinline__ void ldsm4t(uint32_t* r, uint32_t addr) {
    asm volatile("ldmatrix.sync.aligned.m8n8.x4.trans.shared.b16 {%0,%1,%2,%3}, [%4];"
                 : "=r"(r[0]), "=r"(r[1]), "=r"(r[2]), "=r"(r[3]) : "r"(addr));
}
__device__ __forceinline__ void mma_f16(float* c, const uint32_t* a, const uint32_t* b) {
    asm volatile("mma.sync.aligned.m16n8k16.row.col.f32.f16.f16.f32 "
                 "{%0,%1,%2,%3}, {%4,%5,%6,%7}, {%8,%9}, {%0,%1,%2,%3};"
                 : "+f"(c[0]), "+f"(c[1]), "+f"(c[2]), "+f"(c[3])
                 : "r"(a[0]), "r"(a[1]), "r"(a[2]), "r"(a[3]), "r"(b[0]), "r"(b[1]));
}

// ---------------------------------------------------------------------------
// MERGED PROLOGUE: blocks [0, BA_BLOCKS) build A via flash-softmax; blocks
// [BA_BLOCKS, +ENC_BLOCKS) run the encoder (writes fp16 field only).
// ---------------------------------------------------------------------------
#define BA_BLOCKS 128
#define BA_NPB 32
#define BA_CH 1024
#define ENC_BLOCKS 512

__global__ void __launch_bounds__(256) prologue_kernel(
    const float* __restrict__ emb,
    const float* __restrict__ hist,
    const float* __restrict__ tid_emb, const float* __restrict__ diw_emb,
    const float* __restrict__ t2f_w,   const float* __restrict__ t2f_b,
    const float* __restrict__ w1, const float* __restrict__ b1,
    const float* __restrict__ w2, const float* __restrict__ b2)
{
    __shared__ __align__(16) char sbuf[BA_CH * EMBm * 4];   // 40960 B
    int tid = threadIdx.x;

    if (blockIdx.x < BA_BLOCKS) {
        float* semb = (float*)sbuf;
        int nl = tid >> 3;
        int ml = tid & 7;
        int n = blockIdx.x * BA_NPB + nl;

        float en[EMBm];
        {
            const float2* ep = (const float2*)(emb + (size_t)n * EMBm);
            #pragma unroll
            for (int k = 0; k < 5; k++) {
                float2 v = ep[k];
                en[2*k] = v.x; en[2*k+1] = v.y;
            }
        }

        float mx = 0.f, sum = 0.f;                  // relu >= 0
        for (int c = 0; c < Nn / BA_CH; c++) {
            const float4* src = (const float4*)(emb + (size_t)c * BA_CH * EMBm);
            float4* dst = (float4*)semb;
            #pragma unroll
            for (int k = 0; k < (BA_CH*EMBm/4)/256; k++)
                dst[tid + k*256] = src[tid + k*256];
            __syncthreads();
            #pragma unroll 4
            for (int i = 0; i < BA_CH/8; i++) {
                int m = i*8 + ml;
                const float2* sp = (const float2*)(semb + m * EMBm);
                float2 p0 = sp[0], p1 = sp[1], p2 = sp[2], p3 = sp[3], p4 = sp[4];
                float d = en[0]*p0.x + en[1]*p0.y + en[2]*p1.x + en[3]*p1.y
                        + en[4]*p2.x + en[5]*p2.y + en[6]*p3.x + en[7]*p3.y
                        + en[8]*p4.x + en[9]*p4.y;
                d = fmaxf(d, 0.f);
                if (d > mx) { sum *= expf(mx - d); mx = d; }
                sum += expf(d - mx);
            }
            __syncthreads();
        }
        #pragma unroll
        for (int o = 1; o < 8; o <<= 1) {
            float m2 = __shfl_xor_sync(0xffffffffu, mx, o);
            float s2 = __shfl_xor_sync(0xffffffffu, sum, o);
            float M = fmaxf(mx, m2);
            sum = sum * expf(mx - M) + s2 * expf(m2 - M);
            mx = M;
        }
        float inv = 1.f / sum;

        for (int c = 0; c < Nn / BA_CH; c++) {
            const float4* src = (const float4*)(emb + (size_t)c * BA_CH * EMBm);
            float4* dst = (float4*)semb;
            #pragma unroll
            for (int k = 0; k < (BA_CH*EMBm/4)/256; k++)
                dst[tid + k*256] = src[tid + k*256];
            __syncthreads();
            #pragma unroll 4
            for (int i = 0; i < BA_CH/8; i++) {
                int m = i*8 + ml;
                const float2* sp = (const float2*)(semb + m * EMBm);
                float2 p0 = sp[0], p1 = sp[1], p2 = sp[2], p3 = sp[3], p4 = sp[4];
                float d = en[0]*p0.x + en[1]*p0.y + en[2]*p1.x + en[3]*p1.y
                        + en[4]*p2.x + en[5]*p2.y + en[6]*p3.x + en[7]*p3.y
                        + en[8]*p4.x + en[9]*p4.y;
                d = fmaxf(d, 0.f);
                g_Ah[(size_t)n*Nn + c*BA_CH + m] = __float2half_rn(expf(d - mx) * inv);
            }
            __syncthreads();
        }
        return;
    }

    // ----------------- encoder -----------------
    float* s_w1  = (float*)sbuf;
    float* s_w2  = s_w1 + Ll*Cc*HDm;
    float* s_t2f = s_w2 + HDm*FDm;
    float* s_b1  = s_t2f + 2*TDm*FDm;
    float* s_b2  = s_b1 + HDm;
    float* s_t2fb= s_b2 + FDm;

    for (int i = tid; i < Ll*Cc*HDm; i += 256) s_w1[i] = w1[i];
    for (int i = tid; i < HDm*FDm;   i += 256) s_w2[i] = w2[i];
    for (int i = tid; i < 2*TDm*FDm; i += 256) s_t2f[i] = t2f_w[i];
    if (tid < HDm) s_b1[tid] = b1[tid];
    if (tid < FDm) { s_b2[tid] = b2[tid]; s_t2fb[tid] = t2f_b[tid]; }
    __syncthreads();

    int lane = tid & 31;
    int gw = ((blockIdx.x - BA_BLOCKS) * 256 + tid) >> 5;

    for (int it = 0; it < (Bb*Nn)/(ENC_BLOCKS*8); it++) {
        int P = it * (ENC_BLOCKS*8) + gw;
        int n = P & (Nn - 1);
        int b = P >> 12;

        const float* hb = hist + ((size_t)b * Ll * Nn + n) * Cc;
        float x[Ll*Cc];
        #pragma unroll
        for (int l = 0; l < Ll; l++)
            #pragma unroll
            for (int c = 0; c < Cc; c++)
                x[l*Cc + c] = hb[(size_t)l * Nn * Cc + c];

        float h0 = s_b1[lane], h1 = s_b1[32 + lane];
        #pragma unroll
        for (int k = 0; k < Ll*Cc; k++) {
            h0 = fmaf(x[k], s_w1[k*HDm + lane],      h0);
            h1 = fmaf(x[k], s_w1[k*HDm + 32 + lane], h1);
        }
        h0 = fmaxf(h0, 0.f); h1 = fmaxf(h1, 0.f);

        float acc = s_b2[lane];
        #pragma unroll
        for (int hh = 0; hh < HDm; hh++) {
            float v = __shfl_sync(0xffffffffu, (hh < 32) ? h0 : h1, hh & 31);
            acc = fmaf(v, s_w2[hh*FDm + lane], acc);
        }

        float v1 = hb[(size_t)(Ll-1)*Nn*Cc + 1];
        float v2 = hb[(size_t)(Ll-1)*Nn*Cc + 2];
        int ti = (int)(v1 * (float)TIDn); ti = min(max(ti, 0), TIDn-1);
        int di = (int)(v2 * (float)DIWn); di = min(max(di, 0), DIWn-1);
        #pragma unroll
        for (int k = 0; k < TDm; k++)
            acc = fmaf(tid_emb[ti*TDm + k], s_t2f[k*FDm + lane], acc);
        #pragma unroll
        for (int k = 0; k < TDm; k++)
            acc = fmaf(diw_emb[di*TDm + k], s_t2f[(TDm + k)*FDm + lane], acc);
        acc += s_t2fb[lane];

        g_Fh[0][(size_t)n * BF + b*FDm + lane] = __float2half_rn(acc);
    }
}

// ---------------------------------------------------------------------------
// FUSED: fp16 GEMM (AF = A @ field) + step-MLP epilogue (+decoder on last).
// CTA 128x128, BK=32, 5-stage cp.async pipeline (distance-4), 2 CTAs/SM.
// Field lives ONLY in fp16 (g_Fh); epilogue x comes from the rbuf buffer.
// ---------------------------------------------------------------------------
#define BKg 32
#define LDAe 40
#define TA_BYTES (128*LDAe*2)          // 10240
#define LDBB 136
#define TB_BYTES (BKg*LDBB*2)          // 8704
#define STG_BYTES (TA_BYTES + TB_BYTES)  // 18944
#define NST 5
#define CSM_PITCH 132
#define CSM_BYTES (128*CSM_PITCH*4)    // 67584
#define WGT_FLOATS (2048+2048+3*1024+160+2048+64+768+12)   // 10220
#define GSMEM (CSM_BYTES + WGT_FLOATS*4)                   // 108464 (>= 5*18944)

__global__ void __launch_bounds__(256, 2) gemm_fused(
    const float* __restrict__ pw1, const float* __restrict__ pb1,
    const float* __restrict__ pw2, const float* __restrict__ pb2,
    const float* __restrict__ win, const float* __restrict__ wst,
    const float* __restrict__ sb,  const float* __restrict__ wout,
    const float* __restrict__ bout, const float* __restrict__ pde_mix,
    const float* __restrict__ dw1, const float* __restrict__ db1,
    const float* __restrict__ dw2, const float* __restrict__ db2,
    float* __restrict__ out,
    int first, int last, int rbuf)
{
    extern __shared__ char smem[];
    uint32_t sbase = smem_to_u32(smem);
    int tid = threadIdx.x;
    int lane = tid & 31;
    int wid = tid >> 5;
    int bcol = blockIdx.x;    // 0..15
    int brow = blockIdx.y;    // 0..31

    const __half* Ah = g_Ah + (size_t)brow * 128 * Nn;
    const __half* Bg = g_Fh[rbuf] + (size_t)bcol * 128;

    int alr = tid >> 1;
    int alc = (tid & 1) * 16;
    size_t gA = (size_t)alr * Nn + alc;
    uint32_t sA = sbase + alr * (LDAe*2) + alc * 2;
    int blr = tid >> 3;
    int blc = (tid & 7) * 16;
    uint32_t sB = sbase + TA_BYTES + blr * (LDBB*2) + blc * 2;

    int warp_m = wid & 1;
    int warp_n = wid >> 1;
    int m_base = warp_m * 64;
    int n_base = warp_n * 32;

    float acc[4][4][4];
    #pragma unroll
    for (int i = 0; i < 4; i++)
        #pragma unroll
        for (int j = 0; j < 4; j++)
            #pragma unroll
            for (int q = 0; q < 4; q++) acc[i][j][q] = 0.f;

    uint32_t a_off[4];
    #pragma unroll
    for (int i = 0; i < 4; i++)
        a_off[i] = (m_base + i*16 + (lane & 15)) * (LDAe*2) + ((lane >> 4) * 8) * 2;
    uint32_t b_off[2];
    {
        int i = lane >> 3;
        #pragma unroll
        for (int nj = 0; nj < 2; nj++)
            b_off[nj] = ((i & 1) * 8 + (lane & 7)) * (LDBB*2)
                      + (n_base + nj*16 + (i >> 1) * 8) * 2;
    }

    const int NIT = Nn / BKg;   // 128

    // prefetch stages 0..3 (distance-4 pipeline)
    #pragma unroll
    for (int p = 0; p < 4; p++) {
        uint32_t d = p * STG_BYTES;
        size_t kg = (size_t)p * BKg;
        cp16(sA + d,              Ah + gA + kg); cp16(sA + d + 16,              Ah + gA + kg + 8);
        const __half* bs = Bg + (kg + blr) * BF + blc;
        cp16(sB + d,              bs);           cp16(sB + d + 16,              bs + 8);
        CP_COMMIT();
    }

    int scur = 0, spre = 4;
    for (int it = 0; it < NIT; it++) {
        CP_WAIT(3);
        __syncthreads();

        if (it + 4 < NIT) {
            uint32_t d = spre * STG_BYTES;
            size_t kg = (size_t)(it + 4) * BKg;
            cp16(sA + d,              Ah + gA + kg); cp16(sA + d + 16,              Ah + gA + kg + 8);
            const __half* bs = Bg + (kg + blr) * BF + blc;
            cp16(sB + d,              bs);           cp16(sB + d + 16,              bs + 8);
        }
        CP_COMMIT();

        uint32_t st = sbase + scur * STG_BYTES;
        #pragma unroll
        for (int kk = 0; kk < 2; kk++) {
            uint32_t koff = kk * 32;
            uint32_t af[4][4];
            #pragma unroll
            for (int i = 0; i < 4; i++)
                ldsm4(af[i], st + a_off[i] + koff);
            uint32_t bf[2][4];
            #pragma unroll
            for (int j = 0; j < 2; j++)
                ldsm4t(bf[j], st + TA_BYTES + b_off[j] + kk * 16 * (LDBB*2));
            #pragma unroll
            for (int i = 0; i < 4; i++)
                #pragma unroll
                for (int na = 0; na < 4; na++)
                    mma_f16(acc[i][na], af[i], &bf[na >> 1][(na & 1) * 2]);
        }
        scur = (scur + 1 < NST) ? scur + 1 : 0;
        spre = (spre + 1 < NST) ? spre + 1 : 0;
    }
    CP_WAIT(0);
    __syncthreads();

    // ---------------- epilogue ----------------
    float* Csm  = (float*)smem;                 // [128][132]
    float* sw1  = (float*)(smem + CSM_BYTES);
    float* sw2  = sw1 + 2048;
    float* swin = sw2 + 2048;
    float* swst = swin + 1024;
    float* swou = swst + 1024;
    float* sbia = swou + 1024;                  // b1[64] b2[32] sb[32] bout[32]
    float* sdw1 = sbia + 160;
    float* sdb1 = sdw1 + 2048;
    float* sdw2 = sdb1 + 64;
    float* sdb2 = sdw2 + 768;

    for (int i = tid; i < 2048; i += 256) { sw1[i] = pw1[i]; sw2[i] = pw2[i]; }
    for (int i = tid; i < 1024; i += 256) { swin[i] = win[i]; swst[i] = wst[i]; swou[i] = wout[i]; }
    if (tid < 64) sbia[tid] = pb1[tid];
    if (tid < 32) { sbia[64+tid] = pb2[tid]; sbia[96+tid] = sb[tid]; sbia[128+tid] = bout[tid]; }
    if (last) {
        for (int i = tid; i < 2048; i += 256) sdw1[i] = dw1[i];
        for (int i = tid; i < 768;  i += 256) sdw2[i] = dw2[i];
        if (tid < 64) sdb1[tid] = db1[tid];
        if (tid < OUTD) sdb2[tid] = db2[tid];
    }

    #pragma unroll
    for (int i = 0; i < 4; i++) {
        int r = m_base + i*16 + (lane >> 2);
        #pragma unroll
        for (int na = 0; na < 4; na++) {
            int c = n_base + na*8 + 2*(lane & 3);
            Csm[r*CSM_PITCH + c]       = acc[i][na][0];
            Csm[r*CSM_PITCH + c + 1]   = acc[i][na][1];
            Csm[(r+8)*CSM_PITCH + c]   = acc[i][na][2];
            Csm[(r+8)*CSM_PITCH + c+1] = acc[i][na][3];
        }
    }
    __syncthreads();

    float alpha = 1.f / (1.f + expf(-pde_mix[0]));
    const float dtc = 1.f / NSTEPS;
    int wbuf = rbuf ^ 1;

    #pragma unroll
    for (int q = 0; q < 2; q++) {
        int P = q * 256 + tid;
        int m_loc = P >> 2;
        int bg = P & 3;
        int n_glob = brow*128 + m_loc;
        int b_glob = bcol*4 + bg;
        size_t pidx = (size_t)n_glob * Bb + b_glob;
        const __half* fhr = g_Fh[rbuf] + pidx * FDm;
        float* sg = g_state + pidx * FDm;
        __half* fh = g_Fh[wbuf] + pidx * FDm;
        const float* crow = Csm + m_loc * CSM_PITCH + bg * 32;

        // x from fp16 field (2x uint4 = 32 halves)
        float x[FDm];
        #pragma unroll
        for (int u = 0; u < 2; u++) {
            uint4 v = *(const uint4*)(fhr + u*16);
            uint32_t w[4] = {v.x, v.y, v.z, v.w};
            #pragma unroll
            for (int p2 = 0; p2 < 4; p2++) {
                float2 f2 = __half22float2(*(const __half2*)&w[p2]);
                x[u*16 + p2*4 + 0] = f2.x;
                x[u*16 + p2*4 + 1] = f2.y;
                float2 g2 = __half22float2(*(((const __half2*)&w[p2])));
                (void)g2;
            }
        }
        // NOTE: the above unpacked only 8 halves per uint4 incorrectly; redo plainly:
        #pragma unroll
        for (int i = 0; i < FDm/2; i++) {
            float2 f2 = __half22float2(*(const __half2*)(fhr + 2*i));
            x[2*i] = f2.x; x[2*i + 1] = f2.y;
        }

        float nf[FDm];
        #pragma unroll
        for (int f = 0; f < FDm; f++) nf[f] = sbia[64 + f];
        #pragma unroll
        for (int half = 0; half < 2; half++) {
            float h[32];
            #pragma unroll
            for (int hh = 0; hh < 32; hh++) h[hh] = sbia[half*32 + hh];
            #pragma unroll
            for (int k = 0; k < FDm; k++) {
                float xk = x[k];
                #pragma unroll
                for (int hh = 0; hh < 32; hh++)
                    h[hh] = fmaf(xk, sw1[k*HDm + half*32 + hh], h[hh]);
            }
            #pragma unroll
            for (int hh = 0; hh < 32; hh++) {
                float hv = fmaxf(h[hh], 0.f);
                #pragma unroll
                for (int f = 0; f < FDm; f++)
                    nf[f] = fmaf(hv, sw2[(half*32 + hh)*FDm + f], nf[f]);
            }
        }

        #pragma unroll
        for (int f = 0; f < FDm; f++) {
            float af2 = crow[f];
            x[f] = x[f] + (alpha*(af2 - x[f]) + (1.f - alpha)*nf[f]) * dtc;
        }

        float stv[FDm];
        if (first) {
            #pragma unroll
            for (int f = 0; f < FDm; f++) stv[f] = 0.f;
        } else {
            #pragma unroll
            for (int i = 0; i < 8; i++) *(float4*)&stv[i*4] = *(const float4*)(sg + i*4);
        }

        float sa[FDm];
        #pragma unroll
        for (int f = 0; f < FDm; f++) sa[f] = sbia[96 + f];
        #pragma unroll
        for (int k = 0; k < FDm; k++) {
            float fk = x[k], sk = stv[k];
            #pragma unroll
            for (int f = 0; f < FDm; f++) {
                sa[f] = fmaf(fk, swin[k*FDm + f], sa[f]);
                sa[f] = fmaf(sk, swst[k*FDm + f], sa[f]);
            }
        }
        #pragma unroll
        for (int f = 0; f < FDm; f++) sa[f] = tanhf(sa[f]);

        float fo[FDm];
        #pragma unroll
        for (int f = 0; f < FDm; f++) fo[f] = x[f] + sbia[128 + f];
        #pragma unroll
        for (int k = 0; k < FDm; k++) {
            float sk = sa[k];
            #pragma unroll
            for (int f = 0; f < FDm; f++)
                fo[f] = fmaf(sk, swou[k*FDm + f], fo[f]);
        }

        if (!last) {
            #pragma unroll
            for (int i = 0; i < 8; i++) *(float4*)(sg + i*4) = *(float4*)&sa[i*4];
            #pragma unroll
            for (int f = 0; f < FDm; f += 2)
                *(__half2*)(fh + f) = __floats2half2_rn(fo[f], fo[f+1]);
        } else {
            float pred[OUTD];
            #pragma unroll
            for (int o = 0; o < OUTD; o++) pred[o] = sdb2[o];
            #pragma unroll
            for (int half = 0; half < 2; half++) {
                float hd[32];
                #pragma unroll
                for (int hh = 0; hh < 32; hh++) hd[hh] = sdb1[half*32 + hh];
                #pragma unroll
                for (int k = 0; k < FDm; k++) {
                    float fk = fo[k];
                    #pragma unroll
                    for (int hh = 0; hh < 32; hh++)
                        hd[hh] = fmaf(fk, sdw1[k*HDm + half*32 + hh], hd[hh]);
                }
                #pragma unroll
                for (int hh = 0; hh < 32; hh++) {
                    float hv = fmaxf(hd[hh], 0.f);
                    #pragma unroll
                    for (int o = 0; o < OUTD; o++)
                        pred[o] = fmaf(hv, sdw2[(half*32 + hh)*OUTD + o], pred[o]);
                }
            }
            #pragma unroll
            for (int o = 0; o < OUTD; o++)
                out[((size_t)b_glob*OUTD + o)*Nn + n_glob] = pred[o];
        }
    }
}

// ---------------------------------------------------------------------------
extern "C" void kernel_launch(void* const* d_in, const int* in_sizes, int n_in,
                              void* d_out, int out_size)
{
    const float* hist     = (const float*)d_in[0];
    const float* tid_emb  = (const float*)d_in[5];
    const float* diw_emb  = (const float*)d_in[6];
    const float* t2f_w    = (const float*)d_in[7];
    const float* t2f_b    = (const float*)d_in[8];
    const float* enc_w1   = (const float*)d_in[9];
    const float* enc_b1   = (const float*)d_in[10];
    const float* enc_w2   = (const float*)d_in[11];
    const float* enc_b2   = (const float*)d_in[12];
    const float* node_emb = (const float*)d_in[13];
    const float* pde_w1   = (const float*)d_in[14];
    const float* pde_b1   = (const float*)d_in[15];
    const float* pde_w2   = (const float*)d_in[16];
    const float* pde_b2   = (const float*)d_in[17];
    const float* ss_win   = (const float*)d_in[18];
    const float* ss_wst   = (const float*)d_in[19];
    const float* ss_b     = (const float*)d_in[20];
    const float* ss_wout  = (const float*)d_in[21];
    const float* ss_bout  = (const float*)d_in[22];
    const float* dec_w1   = (const float*)d_in[23];
    const float* dec_b1   = (const float*)d_in[24];
    const float* dec_w2   = (const float*)d_in[25];
    const float* dec_b2   = (const float*)d_in[26];
    const float* pde_mix  = (const float*)d_in[27];

    static int smem_set = 0;
    if (!smem_set) {
        cudaFuncSetAttribute(gemm_fused, cudaFuncAttributeMaxDynamicSharedMemorySize, GSMEM);
        smem_set = 1;
    }

    prologue_kernel<<<BA_BLOCKS + ENC_BLOCKS, 256>>>(
        node_emb, hist, tid_emb, diw_emb, t2f_w, t2f_b,
        enc_w1, enc_b1, enc_w2, enc_b2);

    for (int s = 0; s < NSTEPS; s++) {
        gemm_fused<<<dim3(BF/128, Nn/128), 256, GSMEM>>>(
            pde_w1, pde_b1, pde_w2, pde_b2,
            ss_win, ss_wst, ss_b, ss_wout, ss_bout, pde_mix,
            dec_w1, dec_b1, dec_w2, dec_b2, (float*)d_out,
            s == 0, s == NSTEPS-1, s & 1);
    }
}